// round 14
// baseline (speedup 1.0000x reference)
#include <cuda_runtime.h>
#include <cuda_bf16.h>
#include <math.h>
#include <stdint.h>

// Problem constants (fixed shapes)
#define B     2048
#define HIN   128
#define WIN   128
#define S1    64
#define S2    64
#define KDIM  (S1*S2)     // 4096
#define NECK  512
#define KSEL  256
#define SLOTS 16

#define CHUNKS 16
#define KC (KDIM / CHUNKS)    // 256 k per split-K chunk

// Scratch (static __device__ arrays — allocation-free per harness rules)
__device__ float g_pooled[(size_t)B * KDIM];              // 32 MB
__device__ float g_part[CHUNKS][(size_t)B * NECK];        // 64 MB

// ---------------- packed f32x2 helpers (Blackwell sm_103a) -----------------
__device__ __forceinline__ unsigned long long pack2(float lo, float hi) {
    unsigned long long r;
    asm("mov.b64 %0, {%1, %2};" : "=l"(r) : "f"(lo), "f"(hi));
    return r;
}
__device__ __forceinline__ void fma2(unsigned long long& d,
                                     unsigned long long a,
                                     unsigned long long b) {
    asm("fma.rn.f32x2 %0, %1, %2, %3;" : "=l"(d) : "l"(a), "l"(b), "l"(d));
}
__device__ __forceinline__ float2 unpack2(unsigned long long v) {
    float lo, hi;
    asm("mov.b64 {%0, %1}, %2;" : "=f"(lo), "=f"(hi) : "l"(v));
    return make_float2(lo, hi);
}

// ---------------------------------------------------------------------------
// Kernel 1: 2x2 mean pool (verbatim; ~25us, 77% DRAM = at floor)
// ---------------------------------------------------------------------------
__global__ void pool_kernel(const float* __restrict__ x) {
    int idx = blockIdx.x * blockDim.x + threadIdx.x;   // 0 .. B*2048-1
    if (idx >= B * KDIM / 2) return;
    int b = idx >> 11;
    int r = (idx >> 5) & 63;
    int c = idx & 31;
    const float4* row0 = reinterpret_cast<const float4*>(
        x + ((size_t)b * HIN + 2 * r) * WIN);
    const float4* row1 = row0 + (WIN / 4);
    float4 p0 = row0[c];
    float4 p1 = row1[c];
    float2 o;
    o.x = 0.25f * ((p0.x + p0.y) + (p1.x + p1.y));
    o.y = 0.25f * ((p0.z + p0.w) + (p1.z + p1.w));
    reinterpret_cast<float2*>(g_pooled)[idx] = o;
}

// ---------------------------------------------------------------------------
// Kernel 2: split-K SGEMM, fma.rn.f32x2, M-paired accumulators,
// PRE-DUPLICATED B in smem (no pack MOVs in the inner loop).
// Tile 128(M) x 128(N) x 16(K), 128 threads, per-thread 16Mx8N microtile.
// Per-(m,n) k-chain: sequential ascending fma2 over KC=256, identical to
// R11-R13 => g_part bitwise unchanged.
// ---------------------------------------------------------------------------
#define BM 128
#define BN 128
#define BK 16
#define LDA_W 132    // float  elems per As row (528B stride)
#define LDB_W 130    // float2 elems per Bs row (1040B stride)

__global__ __launch_bounds__(128)
void sgemm_split_kernel(const float* __restrict__ Wm) {
    __shared__ float  As[2][BK][LDA_W];    // [kk][m]          2 x 8.25 KB
    __shared__ float2 Bs[2][BK][LDB_W];    // [kk][n] dup pairs 2 x 16.25 KB

    const int tid = threadIdx.x;
    const int tm  = tid >> 4;         // 0..7  -> m base = tm*16
    const int tn  = tid & 15;         // 0..15 -> n base = tn*8
    const int n0  = blockIdx.x * BN;
    const int m0  = blockIdx.y * BM;
    const int kb  = blockIdx.z * KC;

    // Staging: thread owns row `tid` of both tiles; 4 float4 along k each.
    const float* Ag = g_pooled + (size_t)(m0 + tid) * KDIM + kb;
    const float* Bg = Wm       + (size_t)(n0 + tid) * KDIM + kb;

    unsigned long long acc[8][8];   // [m-pair][n]
    const unsigned long long z2 = pack2(0.f, 0.f);
    #pragma unroll
    for (int i = 0; i < 8; i++)
        #pragma unroll
        for (int j = 0; j < 8; j++) acc[i][j] = z2;

    // ---- prefetch tile 0 into regs, scatter to buffer 0 ----
    float4 pa[4], pb[4];
    #pragma unroll
    for (int c = 0; c < 4; c++) {
        pa[c] = *reinterpret_cast<const float4*>(Ag + 4 * c);
        pb[c] = *reinterpret_cast<const float4*>(Bg + 4 * c);
    }
    #pragma unroll
    for (int c = 0; c < 4; c++) {
        float va[4] = {pa[c].x, pa[c].y, pa[c].z, pa[c].w};
        float vb[4] = {pb[c].x, pb[c].y, pb[c].z, pb[c].w};
        #pragma unroll
        for (int e = 0; e < 4; e++) {
            As[0][4 * c + e][tid] = va[e];
            Bs[0][4 * c + e][tid] = make_float2(vb[e], vb[e]);
        }
    }
    __syncthreads();

    const int NT = KC / BK;   // 16 tiles
    for (int t = 0; t < NT; t++) {
        const int cur = t & 1;
        const int nxt = cur ^ 1;

        // prefetch next tile (global -> regs), overlapped with compute
        if (t + 1 < NT) {
            #pragma unroll
            for (int c = 0; c < 4; c++) {
                pa[c] = *reinterpret_cast<const float4*>(Ag + (t + 1) * BK + 4 * c);
                pb[c] = *reinterpret_cast<const float4*>(Bg + (t + 1) * BK + 4 * c);
            }
        }

        // compute 16 k-steps on current buffer
        #pragma unroll
        for (int kk = 0; kk < BK; kk++) {
            // A: 16 m-values as 8 natural (m,m+1) 64-bit lanes
            const ulonglong2* am =
                reinterpret_cast<const ulonglong2*>(&As[cur][kk][tm * 16]);
            ulonglong2 aq0 = am[0];
            ulonglong2 aq1 = am[1];
            ulonglong2 aq2 = am[2];
            ulonglong2 aq3 = am[3];
            unsigned long long ap[8] = {aq0.x, aq0.y, aq1.x, aq1.y,
                                        aq2.x, aq2.y, aq3.x, aq3.y};
            // B: 8 pre-duplicated (b,b) pairs read directly — no packs
            const ulonglong2* bm =
                reinterpret_cast<const ulonglong2*>(&Bs[cur][kk][tn * 8]);
            ulonglong2 bq0 = bm[0];
            ulonglong2 bq1 = bm[1];
            ulonglong2 bq2 = bm[2];
            ulonglong2 bq3 = bm[3];
            unsigned long long bp[8] = {bq0.x, bq0.y, bq1.x, bq1.y,
                                        bq2.x, bq2.y, bq3.x, bq3.y};

            #pragma unroll
            for (int i = 0; i < 8; i++)
                #pragma unroll
                for (int j = 0; j < 8; j++)
                    fma2(acc[i][j], ap[i], bp[j]);
        }

        // scatter prefetched tile into the other buffer
        if (t + 1 < NT) {
            #pragma unroll
            for (int c = 0; c < 4; c++) {
                float va[4] = {pa[c].x, pa[c].y, pa[c].z, pa[c].w};
                float vb[4] = {pb[c].x, pb[c].y, pb[c].z, pb[c].w};
                #pragma unroll
                for (int e = 0; e < 4; e++) {
                    As[nxt][4 * c + e][tid] = va[e];
                    Bs[nxt][4 * c + e][tid] = make_float2(vb[e], vb[e]);
                }
            }
        }
        __syncthreads();
    }

    // store partials: acc[i][j] = rows (2i, 2i+1) at col j
    float* outp = g_part[blockIdx.z];
    #pragma unroll
    for (int i = 0; i < 8; i++) {
        float lo[8], hi[8];
        #pragma unroll
        for (int j = 0; j < 8; j++) {
            float2 v = unpack2(acc[i][j]);
            lo[j] = v.x;
            hi[j] = v.y;
        }
        size_t base0 = (size_t)(m0 + tm * 16 + 2 * i)     * NECK + n0 + tn * 8;
        size_t base1 = (size_t)(m0 + tm * 16 + 2 * i + 1) * NECK + n0 + tn * 8;
        *reinterpret_cast<float4*>(outp + base0)     = make_float4(lo[0], lo[1], lo[2], lo[3]);
        *reinterpret_cast<float4*>(outp + base0 + 4) = make_float4(lo[4], lo[5], lo[6], lo[7]);
        *reinterpret_cast<float4*>(outp + base1)     = make_float4(hi[0], hi[1], hi[2], hi[3]);
        *reinterpret_cast<float4*>(outp + base1 + 4) = make_float4(hi[4], hi[5], hi[6], hi[7]);
    }
}

// ---------------------------------------------------------------------------
// Kernel 3: FUSED split-K reduce + exact radix-bisection top-256 select
// + R4-proven hedge + broadcast. NOW 512 threads (1 element/thread):
// halves the barrier count in the radix loop. Same arithmetic => same
// thresh/sub/weights => output bitwise identical.
// ---------------------------------------------------------------------------
__global__ __launch_bounds__(512)
void topk_kernel(float* __restrict__ out) {
    __shared__ float sval[NECK];
    __shared__ uint32_t smax[16];
    const int b   = blockIdx.x;
    const int tid = threadIdx.x;

    // Reduce partials (identical pairwise tree => feat bitwise unchanged)
    const size_t off = (size_t)b * NECK + tid;
    float p[CHUNKS];
    #pragma unroll
    for (int c = 0; c < CHUNKS; c++) p[c] = g_part[c][off];
    float s0 = ((p[0]  + p[1])  + (p[2]  + p[3]));
    float s1 = ((p[4]  + p[5])  + (p[6]  + p[7]));
    float s2 = ((p[8]  + p[9])  + (p[10] + p[11]));
    float s3 = ((p[12] + p[13]) + (p[14] + p[15]));
    float v  = (s0 + s1) + (s2 + s3);
    sval[tid] = v;
    const uint32_t key = __float_as_uint(fabsf(v));

    // Exact 256th-largest key via MSB->LSB bisection (31 barriers).
    uint32_t prefix = 0;
    #pragma unroll 1
    for (int bit = 30; bit >= 0; bit--) {
        const uint32_t test = prefix | (1u << bit);
        if (__syncthreads_count(key >= test) >= KSEL) prefix = test;
    }
    const uint32_t tbits = prefix;

    // sub = 257th largest, exactly as a full sort would give.
    const int ct = __syncthreads_count(key >= tbits);
    uint32_t sb;
    if (ct >= KSEL + 1) {
        sb = tbits;
    } else {
        uint32_t m = (key < tbits) ? key : 0u;
        #pragma unroll
        for (int o = 16; o; o >>= 1) {
            uint32_t other = __shfl_down_sync(0xFFFFFFFFu, m, o);
            if (other > m) m = other;
        }
        if ((tid & 31) == 0) smax[tid >> 5] = m;
        __syncthreads();
        m = smax[0];
        #pragma unroll
        for (int w = 1; w < 16; w++) m = max(m, smax[w]);
        sb = m;
    }

    const float thresh = __uint_as_float(tbits);
    const float sub    = __uint_as_float(sb);

    // R4-proven hedge (identical arithmetic)
    const float eps = 6e-6f * thresh + 1e-30f;
    const float g   = thresh - sub;
    float q = 0.5f * exp2f(-g / eps);
    if (q < 0.004f) q = 0.0f;

    {
        float a = fabsf(v);
        float w;
        if (a >= thresh)      w = (a == thresh) ? (1.0f - q) : 1.0f;
        else if (a == sub)    w = q;
        else                  w = 0.0f;
        sval[tid] = v * w;
    }
    __syncthreads();

    // Broadcast-write 16 slots, float4-vectorized (512 thr x 4 iters)
    const float4* v4 = reinterpret_cast<const float4*>(sval);
    float4* out4 = reinterpret_cast<float4*>(out) + (size_t)b * SLOTS * (NECK / 4);
    #pragma unroll
    for (int t = tid; t < SLOTS * (NECK / 4); t += 512) {
        int slot = t >> 7;
        int i    = t & 127;
        out4[slot * (NECK / 4) + i] = v4[i];
    }
}

// ---------------------------------------------------------------------------
extern "C" void kernel_launch(void* const* d_in, const int* in_sizes, int n_in,
                              void* d_out, int out_size) {
    const float* x  = (const float*)d_in[0];   // [2048,128,128]
    const float* Wm = (const float*)d_in[1];   // [512,4096]
    float* out = (float*)d_out;                // [2048,16,512]

    pool_kernel<<<(B * KDIM / 2) / 256, 256>>>(x);
    sgemm_split_kernel<<<dim3(NECK / BN, B / BM, CHUNKS), 128>>>(Wm);
    topk_kernel<<<B, 512>>>(out);
}

// round 15
// speedup vs baseline: 1.6925x; 1.6925x over previous
#include <cuda_runtime.h>
#include <cuda_bf16.h>
#include <math.h>
#include <stdint.h>

// Problem constants (fixed shapes)
#define B     2048
#define HIN   128
#define WIN   128
#define S1    64
#define S2    64
#define KDIM  (S1*S2)     // 4096
#define NECK  512
#define KSEL  256
#define SLOTS 16

#define CHUNKS 16
#define KC (KDIM / CHUNKS)    // 256 k per split-K chunk

// Scratch (static __device__ arrays — allocation-free per harness rules)
__device__ float g_pooled[(size_t)B * KDIM];              // 32 MB
__device__ float g_part[CHUNKS][(size_t)B * NECK];        // 64 MB

// ---------------- packed f32x2 helpers (Blackwell sm_103a) -----------------
__device__ __forceinline__ unsigned long long pack2(float lo, float hi) {
    unsigned long long r;
    asm("mov.b64 %0, {%1, %2};" : "=l"(r) : "f"(lo), "f"(hi));
    return r;
}
__device__ __forceinline__ void fma2(unsigned long long& d,
                                     unsigned long long a,
                                     unsigned long long b) {
    asm("fma.rn.f32x2 %0, %1, %2, %3;" : "=l"(d) : "l"(a), "l"(b), "l"(d));
}
__device__ __forceinline__ float2 unpack2(unsigned long long v) {
    float lo, hi;
    asm("mov.b64 {%0, %1}, %2;" : "=f"(lo), "=f"(hi) : "l"(v));
    return make_float2(lo, hi);
}

// ---------------------------------------------------------------------------
// Kernel 1: 2x2 mean pool (verbatim; ~25us, 77% DRAM = at floor)
// ---------------------------------------------------------------------------
__global__ void pool_kernel(const float* __restrict__ x) {
    int idx = blockIdx.x * blockDim.x + threadIdx.x;   // 0 .. B*2048-1
    if (idx >= B * KDIM / 2) return;
    int b = idx >> 11;
    int r = (idx >> 5) & 63;
    int c = idx & 31;
    const float4* row0 = reinterpret_cast<const float4*>(
        x + ((size_t)b * HIN + 2 * r) * WIN);
    const float4* row1 = row0 + (WIN / 4);
    float4 p0 = row0[c];
    float4 p1 = row1[c];
    float2 o;
    o.x = 0.25f * ((p0.x + p0.y) + (p1.x + p1.y));
    o.y = 0.25f * ((p0.z + p0.w) + (p1.z + p1.w));
    reinterpret_cast<float2*>(g_pooled)[idx] = o;
}

// ---------------------------------------------------------------------------
// Kernel 2: split-K SGEMM (R13 version, VERBATIM — the measured-best GEMM).
// fma.rn.f32x2, M-paired accumulators, B packed in regs (8 MOV/kk).
// Tile 128(M) x 128(N) x 16(K), 128 threads, per-thread 16Mx8N microtile.
// Per-(m,n) k-chain: sequential ascending fma2 over KC=256 => g_part
// bitwise unchanged vs all passing rounds.
// ---------------------------------------------------------------------------
#define BM 128
#define BN 128
#define BK 16
#define LDS_W (BM + 4)    // 132 floats row stride (528B, 16B multiple)

__global__ __launch_bounds__(128)
void sgemm_split_kernel(const float* __restrict__ Wm) {
    __shared__ float As[2][BK][LDS_W];   // [kk][m]
    __shared__ float Bs[2][BK][LDS_W];   // [kk][n]

    const int tid = threadIdx.x;
    const int tm  = tid >> 4;         // 0..7  -> m base = tm*16
    const int tn  = tid & 15;         // 0..15 -> n base = tn*8
    const int n0  = blockIdx.x * BN;
    const int m0  = blockIdx.y * BM;
    const int kb  = blockIdx.z * KC;

    const float* Ag = g_pooled + (size_t)(m0 + tid) * KDIM + kb;
    const float* Bg = Wm       + (size_t)(n0 + tid) * KDIM + kb;

    unsigned long long acc[8][8];   // [m-pair][n]
    const unsigned long long z2 = pack2(0.f, 0.f);
    #pragma unroll
    for (int i = 0; i < 8; i++)
        #pragma unroll
        for (int j = 0; j < 8; j++) acc[i][j] = z2;

    float4 pa[4], pb[4];
    #pragma unroll
    for (int c = 0; c < 4; c++) {
        pa[c] = *reinterpret_cast<const float4*>(Ag + 4 * c);
        pb[c] = *reinterpret_cast<const float4*>(Bg + 4 * c);
    }
    #pragma unroll
    for (int c = 0; c < 4; c++) {
        float va[4] = {pa[c].x, pa[c].y, pa[c].z, pa[c].w};
        float vb[4] = {pb[c].x, pb[c].y, pb[c].z, pb[c].w};
        #pragma unroll
        for (int e = 0; e < 4; e++) {
            As[0][4 * c + e][tid] = va[e];
            Bs[0][4 * c + e][tid] = vb[e];
        }
    }
    __syncthreads();

    const int NT = KC / BK;   // 16 tiles
    for (int t = 0; t < NT; t++) {
        const int cur = t & 1;
        const int nxt = cur ^ 1;

        if (t + 1 < NT) {
            #pragma unroll
            for (int c = 0; c < 4; c++) {
                pa[c] = *reinterpret_cast<const float4*>(Ag + (t + 1) * BK + 4 * c);
                pb[c] = *reinterpret_cast<const float4*>(Bg + (t + 1) * BK + 4 * c);
            }
        }

        #pragma unroll
        for (int kk = 0; kk < BK; kk++) {
            const ulonglong2* am =
                reinterpret_cast<const ulonglong2*>(&As[cur][kk][tm * 16]);
            ulonglong2 aq0 = am[0];
            ulonglong2 aq1 = am[1];
            ulonglong2 aq2 = am[2];
            ulonglong2 aq3 = am[3];
            unsigned long long ap[8] = {aq0.x, aq0.y, aq1.x, aq1.y,
                                        aq2.x, aq2.y, aq3.x, aq3.y};
            float4 b0 = *reinterpret_cast<const float4*>(&Bs[cur][kk][tn * 8]);
            float4 b1 = *reinterpret_cast<const float4*>(&Bs[cur][kk][tn * 8 + 4]);
            unsigned long long bp[8];
            bp[0] = pack2(b0.x, b0.x); bp[1] = pack2(b0.y, b0.y);
            bp[2] = pack2(b0.z, b0.z); bp[3] = pack2(b0.w, b0.w);
            bp[4] = pack2(b1.x, b1.x); bp[5] = pack2(b1.y, b1.y);
            bp[6] = pack2(b1.z, b1.z); bp[7] = pack2(b1.w, b1.w);

            #pragma unroll
            for (int i = 0; i < 8; i++)
                #pragma unroll
                for (int j = 0; j < 8; j++)
                    fma2(acc[i][j], ap[i], bp[j]);
        }

        if (t + 1 < NT) {
            #pragma unroll
            for (int c = 0; c < 4; c++) {
                float va[4] = {pa[c].x, pa[c].y, pa[c].z, pa[c].w};
                float vb[4] = {pb[c].x, pb[c].y, pb[c].z, pb[c].w};
                #pragma unroll
                for (int e = 0; e < 4; e++) {
                    As[nxt][4 * c + e][tid] = va[e];
                    Bs[nxt][4 * c + e][tid] = vb[e];
                }
            }
        }
        __syncthreads();
    }

    float* outp = g_part[blockIdx.z];
    #pragma unroll
    for (int i = 0; i < 8; i++) {
        float lo[8], hi[8];
        #pragma unroll
        for (int j = 0; j < 8; j++) {
            float2 v = unpack2(acc[i][j]);
            lo[j] = v.x;
            hi[j] = v.y;
        }
        size_t base0 = (size_t)(m0 + tm * 16 + 2 * i)     * NECK + n0 + tn * 8;
        size_t base1 = (size_t)(m0 + tm * 16 + 2 * i + 1) * NECK + n0 + tn * 8;
        *reinterpret_cast<float4*>(outp + base0)     = make_float4(lo[0], lo[1], lo[2], lo[3]);
        *reinterpret_cast<float4*>(outp + base0 + 4) = make_float4(lo[4], lo[5], lo[6], lo[7]);
        *reinterpret_cast<float4*>(outp + base1)     = make_float4(hi[0], hi[1], hi[2], hi[3]);
        *reinterpret_cast<float4*>(outp + base1 + 4) = make_float4(hi[4], hi[5], hi[6], hi[7]);
    }
}

// ---------------------------------------------------------------------------
// Kernel 3: FUSED split-K reduce + exact radix-bisection top-256 select
// + R4-proven hedge + broadcast. 512 threads (R14 variant — arithmetic
// identical, fewer barriers).
// ---------------------------------------------------------------------------
__global__ __launch_bounds__(512)
void topk_kernel(float* __restrict__ out) {
    __shared__ float sval[NECK];
    __shared__ uint32_t smax[16];
    const int b   = blockIdx.x;
    const int tid = threadIdx.x;

    const size_t off = (size_t)b * NECK + tid;
    float p[CHUNKS];
    #pragma unroll
    for (int c = 0; c < CHUNKS; c++) p[c] = g_part[c][off];
    float s0 = ((p[0]  + p[1])  + (p[2]  + p[3]));
    float s1 = ((p[4]  + p[5])  + (p[6]  + p[7]));
    float s2 = ((p[8]  + p[9])  + (p[10] + p[11]));
    float s3 = ((p[12] + p[13]) + (p[14] + p[15]));
    float v  = (s0 + s1) + (s2 + s3);
    sval[tid] = v;
    const uint32_t key = __float_as_uint(fabsf(v));

    uint32_t prefix = 0;
    #pragma unroll 1
    for (int bit = 30; bit >= 0; bit--) {
        const uint32_t test = prefix | (1u << bit);
        if (__syncthreads_count(key >= test) >= KSEL) prefix = test;
    }
    const uint32_t tbits = prefix;

    const int ct = __syncthreads_count(key >= tbits);
    uint32_t sb;
    if (ct >= KSEL + 1) {
        sb = tbits;
    } else {
        uint32_t m = (key < tbits) ? key : 0u;
        #pragma unroll
        for (int o = 16; o; o >>= 1) {
            uint32_t other = __shfl_down_sync(0xFFFFFFFFu, m, o);
            if (other > m) m = other;
        }
        if ((tid & 31) == 0) smax[tid >> 5] = m;
        __syncthreads();
        m = smax[0];
        #pragma unroll
        for (int w = 1; w < 16; w++) m = max(m, smax[w]);
        sb = m;
    }

    const float thresh = __uint_as_float(tbits);
    const float sub    = __uint_as_float(sb);

    const float eps = 6e-6f * thresh + 1e-30f;
    const float g   = thresh - sub;
    float q = 0.5f * exp2f(-g / eps);
    if (q < 0.004f) q = 0.0f;

    {
        float a = fabsf(v);
        float w;
        if (a >= thresh)      w = (a == thresh) ? (1.0f - q) : 1.0f;
        else if (a == sub)    w = q;
        else                  w = 0.0f;
        sval[tid] = v * w;
    }
    __syncthreads();

    const float4* v4 = reinterpret_cast<const float4*>(sval);
    float4* out4 = reinterpret_cast<float4*>(out) + (size_t)b * SLOTS * (NECK / 4);
    #pragma unroll
    for (int t = tid; t < SLOTS * (NECK / 4); t += 512) {
        int slot = t >> 7;
        int i    = t & 127;
        out4[slot * (NECK / 4) + i] = v4[i];
    }
}

// ---------------------------------------------------------------------------
extern "C" void kernel_launch(void* const* d_in, const int* in_sizes, int n_in,
                              void* d_out, int out_size) {
    const float* x  = (const float*)d_in[0];   // [2048,128,128]
    const float* Wm = (const float*)d_in[1];   // [512,4096]
    float* out = (float*)d_out;                // [2048,16,512]

    pool_kernel<<<(B * KDIM / 2) / 256, 256>>>(x);
    sgemm_split_kernel<<<dim3(NECK / BN, B / BM, CHUNKS), 128>>>(Wm);
    topk_kernel<<<B, 512>>>(out);
}